// round 3
// baseline (speedup 1.0000x reference)
#include <cuda_runtime.h>
#include <cstddef>

// Problem constants
#define BB 8
#define SS 2048
#define EE 1024
#define NROWS (BB * SS)   // 16384

// ---------------------------------------------------------------------------
// Scratch (device globals: the allocation-guard-legal way to get workspace)
// ---------------------------------------------------------------------------
__device__ float g_h[(size_t)NROWS * EE];   // 64 MB: LN1 output, reused for LN2 output
__device__ float g_q[(size_t)NROWS * EE];   // 64 MB
__device__ float g_k[(size_t)NROWS * EE];   // 64 MB
__device__ float g_v[(size_t)NROWS * EE];   // 64 MB
__device__ float g_o[(size_t)NROWS * EE];   // 64 MB: attention output
__device__ float g_s[(size_t)BB * SS * SS]; // 128 MB: scores / attn weights

// ---------------------------------------------------------------------------
// Block reductions (256 threads, 8 warps)
// ---------------------------------------------------------------------------
__device__ __forceinline__ float blockReduceSum(float v, float* red) {
    #pragma unroll
    for (int o = 16; o > 0; o >>= 1) v += __shfl_xor_sync(0xffffffffu, v, o);
    int t = threadIdx.x;
    if ((t & 31) == 0) red[t >> 5] = v;
    __syncthreads();
    if (t < 32) {
        float r = (t < 8) ? red[t] : 0.0f;
        #pragma unroll
        for (int o = 4; o > 0; o >>= 1) r += __shfl_xor_sync(0xffffffffu, r, o);
        if (t == 0) red[0] = r;
    }
    __syncthreads();
    float out = red[0];
    __syncthreads();   // allow red[] reuse by caller
    return out;
}

__device__ __forceinline__ float blockReduceMax(float v, float* red) {
    #pragma unroll
    for (int o = 16; o > 0; o >>= 1) v = fmaxf(v, __shfl_xor_sync(0xffffffffu, v, o));
    int t = threadIdx.x;
    if ((t & 31) == 0) red[t >> 5] = v;
    __syncthreads();
    if (t < 32) {
        float r = (t < 8) ? red[t] : -3.0e38f;
        #pragma unroll
        for (int o = 4; o > 0; o >>= 1) r = fmaxf(r, __shfl_xor_sync(0xffffffffu, r, o));
        if (t == 0) red[0] = r;
    }
    __syncthreads();
    float out = red[0];
    __syncthreads();
    return out;
}

// ---------------------------------------------------------------------------
// LayerNorm over rows of 1024 (two-pass, matches reference exactly)
// ---------------------------------------------------------------------------
__global__ __launch_bounds__(256) void ln1024(const float* __restrict__ in,
                                              const float* __restrict__ gam,
                                              const float* __restrict__ bet,
                                              float* __restrict__ out) {
    __shared__ float red[8];
    long row = blockIdx.x;
    const float* x = in + row * (long)EE;
    int t = threadIdx.x;
    float4 xv = *reinterpret_cast<const float4*>(&x[t * 4]);

    float s = xv.x + xv.y + xv.z + xv.w;
    s = blockReduceSum(s, red);
    float mu = s * (1.0f / 1024.0f);

    float d0 = xv.x - mu, d1 = xv.y - mu, d2 = xv.z - mu, d3 = xv.w - mu;
    float ss = blockReduceSum(d0 * d0 + d1 * d1 + d2 * d2 + d3 * d3, red);
    float r = rsqrtf(ss * (1.0f / 1024.0f) + 1e-5f);

    float4 g4 = *reinterpret_cast<const float4*>(&gam[t * 4]);
    float4 b4 = *reinterpret_cast<const float4*>(&bet[t * 4]);
    float4 o4;
    o4.x = d0 * r * g4.x + b4.x;
    o4.y = d1 * r * g4.y + b4.y;
    o4.z = d2 * r * g4.z + b4.z;
    o4.w = d3 * r * g4.w + b4.w;
    *reinterpret_cast<float4*>(&out[row * (long)EE + t * 4]) = o4;
}

// ---------------------------------------------------------------------------
// Softmax over rows of 2048 (in place on g_s)
// ---------------------------------------------------------------------------
__global__ __launch_bounds__(256) void softmax2048(float* __restrict__ sc) {
    __shared__ float red[8];
    long row = blockIdx.x;
    float* p = sc + row * (long)SS;
    int t = threadIdx.x;
    float4 a = *reinterpret_cast<const float4*>(&p[t * 8]);
    float4 b = *reinterpret_cast<const float4*>(&p[t * 8 + 4]);

    float m = fmaxf(fmaxf(fmaxf(a.x, a.y), fmaxf(a.z, a.w)),
                    fmaxf(fmaxf(b.x, b.y), fmaxf(b.z, b.w)));
    m = blockReduceMax(m, red);

    a.x = __expf(a.x - m); a.y = __expf(a.y - m);
    a.z = __expf(a.z - m); a.w = __expf(a.w - m);
    b.x = __expf(b.x - m); b.y = __expf(b.y - m);
    b.z = __expf(b.z - m); b.w = __expf(b.w - m);

    float s = (a.x + a.y + a.z + a.w) + (b.x + b.y + b.z + b.w);
    s = blockReduceSum(s, red);
    float inv = 1.0f / s;

    a.x *= inv; a.y *= inv; a.z *= inv; a.w *= inv;
    b.x *= inv; b.y *= inv; b.z *= inv; b.w *= inv;
    *reinterpret_cast<float4*>(&p[t * 8])     = a;
    *reinterpret_cast<float4*>(&p[t * 8 + 4]) = b;
}

// ---------------------------------------------------------------------------
// Tiled SGEMM: C[M,Ncol] = A[M,K] * B  (B is [K,Ncol] row-major if !TRANSB,
// or [Ncol,K] row-major if TRANSB, i.e. C = A*B^T).
// 128x128 tile, BK=8, 256 threads, 8x8 per-thread microtile.
// EPI: 0 = none, 1 = +bias[col], 2 = 2*(acc + bias[col] + resid[row,col])
// blockIdx.z batches with strides sA/sB/sC (elements).
// All dims assumed multiples of tile sizes (true for this problem).
// ---------------------------------------------------------------------------
template <bool TRANSB, int EPI>
__global__ __launch_bounds__(256) void gemm_tile(
    const float* __restrict__ A, const float* __restrict__ Bm,
    float* __restrict__ C,
    const float* __restrict__ bias, const float* __restrict__ resid,
    int M, int Ncol, int K, long sA, long sB, long sC)
{
    A  += (long)blockIdx.z * sA;
    Bm += (long)blockIdx.z * sB;
    C  += (long)blockIdx.z * sC;

    __shared__ float As[8][132];   // +4 pad: conflict-free scatter stores
    __shared__ float Bs[8][132];

    const int tid = threadIdx.x;
    const int tx = tid & 15;          // 0..15 -> col group
    const int ty = tid >> 4;          // 0..15 -> row group
    const int rowBase = blockIdx.y * 128;
    const int colBase = blockIdx.x * 128;

    // Coalesced scalar loads: warp covers 4 rows x 8 k (32B/row sectors)
    const int lk = tid & 7;           // k within tile
    const int lr = tid >> 3;          // 0..31 row within tile

    float acc[8][8];
    #pragma unroll
    for (int i = 0; i < 8; i++)
        #pragma unroll
        for (int j = 0; j < 8; j++) acc[i][j] = 0.0f;

    const float* Aptr = A + (long)(rowBase + lr) * K + lk;
    const float* BptrT = TRANSB ? (Bm + (long)(colBase + lr) * K + lk) : nullptr;

    for (int k0 = 0; k0 < K; k0 += 8) {
        #pragma unroll
        for (int i = 0; i < 4; i++)
            As[lk][lr + i * 32] = Aptr[(long)i * 32 * K + k0];

        if (TRANSB) {
            #pragma unroll
            for (int i = 0; i < 4; i++)
                Bs[lk][lr + i * 32] = BptrT[(long)i * 32 * K + k0];
        } else {
            const int br = tid >> 5;          // 0..7
            const int bc = (tid & 31) * 4;    // 0..124
            float4 bv = *reinterpret_cast<const float4*>(
                &Bm[(long)(k0 + br) * Ncol + colBase + bc]);
            *reinterpret_cast<float4*>(&Bs[br][bc]) = bv;
        }
        __syncthreads();

        #pragma unroll
        for (int kk = 0; kk < 8; ++kk) {
            float af[8], bf[8];
            *reinterpret_cast<float4*>(af)     = *reinterpret_cast<const float4*>(&As[kk][ty * 8]);
            *reinterpret_cast<float4*>(af + 4) = *reinterpret_cast<const float4*>(&As[kk][ty * 8 + 4]);
            *reinterpret_cast<float4*>(bf)     = *reinterpret_cast<const float4*>(&Bs[kk][tx * 8]);
            *reinterpret_cast<float4*>(bf + 4) = *reinterpret_cast<const float4*>(&Bs[kk][tx * 8 + 4]);
            #pragma unroll
            for (int i = 0; i < 8; i++)
                #pragma unroll
                for (int j = 0; j < 8; j++)
                    acc[i][j] += af[i] * bf[j];
        }
        __syncthreads();
    }

    #pragma unroll
    for (int i = 0; i < 8; i++) {
        long row = rowBase + ty * 8 + i;
        float* crow = C + row * (long)Ncol;
        const float* rrow = (EPI == 2) ? (resid + row * (long)Ncol) : nullptr;
        #pragma unroll
        for (int j = 0; j < 8; j += 4) {
            int col = colBase + tx * 8 + j;
            float4 v;
            v.x = acc[i][j + 0]; v.y = acc[i][j + 1];
            v.z = acc[i][j + 2]; v.w = acc[i][j + 3];
            if (EPI >= 1) {
                float4 b4 = *reinterpret_cast<const float4*>(&bias[col]);
                v.x += b4.x; v.y += b4.y; v.z += b4.z; v.w += b4.w;
            }
            if (EPI == 2) {
                float4 r4 = *reinterpret_cast<const float4*>(&rrow[col]);
                v.x = 2.0f * (v.x + r4.x);
                v.y = 2.0f * (v.y + r4.y);
                v.z = 2.0f * (v.z + r4.z);
                v.w = 2.0f * (v.w + r4.w);
            }
            *reinterpret_cast<float4*>(&crow[col]) = v;
        }
    }
}

// ---------------------------------------------------------------------------
// Launch sequence (graph-capturable: kernel launches only)
// ---------------------------------------------------------------------------
extern "C" void kernel_launch(void* const* d_in, const int* in_sizes, int n_in,
                              void* d_out, int out_size) {
    const float* x   = (const float*)d_in[0];
    const float* Wq  = (const float*)d_in[1];
    const float* bq  = (const float*)d_in[2];
    const float* Wk  = (const float*)d_in[3];
    const float* bk  = (const float*)d_in[4];
    const float* Wv  = (const float*)d_in[5];
    const float* bv  = (const float*)d_in[6];
    const float* Wfc = (const float*)d_in[7];
    const float* bfc = (const float*)d_in[8];
    const float* g1  = (const float*)d_in[9];
    const float* b1  = (const float*)d_in[10];
    const float* g2  = (const float*)d_in[11];
    const float* b2  = (const float*)d_in[12];
    float* out = (float*)d_out;

    float *h, *q, *k, *v, *o, *s;
    cudaGetSymbolAddress((void**)&h, g_h);
    cudaGetSymbolAddress((void**)&q, g_q);
    cudaGetSymbolAddress((void**)&k, g_k);
    cudaGetSymbolAddress((void**)&v, g_v);
    cudaGetSymbolAddress((void**)&o, g_o);
    cudaGetSymbolAddress((void**)&s, g_s);

    // 1) h = LN(x; g1, b1)
    ln1024<<<NROWS, 256>>>(x, g1, b1, h);

    // 2) q/k/v = h @ W + b   [16384,1024] x [1024,1024]
    dim3 gw(EE / 128, NROWS / 128, 1);
    gemm_tile<false, 1><<<gw, 256>>>(h, Wq, q, bq, nullptr, NROWS, EE, EE, 0, 0, 0);
    gemm_tile<false, 1><<<gw, 256>>>(h, Wk, k, bk, nullptr, NROWS, EE, EE, 0, 0, 0);
    gemm_tile<false, 1><<<gw, 256>>>(h, Wv, v, bv, nullptr, NROWS, EE, EE, 0, 0, 0);

    // 3) scores = q @ k^T per batch  [2048,2048], K=1024
    dim3 gs(SS / 128, SS / 128, BB);
    gemm_tile<true, 0><<<gs, 256>>>(q, k, s, nullptr, nullptr, SS, SS, EE,
                                    (long)SS * EE, (long)SS * EE, (long)SS * SS);

    // 4) softmax over keys
    softmax2048<<<BB * SS, 256>>>(s);

    // 5) o = attn @ v per batch  [2048,1024], K=2048
    dim3 go(EE / 128, SS / 128, BB);
    gemm_tile<false, 0><<<go, 256>>>(s, v, o, nullptr, nullptr, SS, EE, SS,
                                     (long)SS * SS, (long)SS * EE, (long)SS * EE);

    // 6) h = LN(o; g2, b2)   (reuse g_h)
    ln1024<<<NROWS, 256>>>(o, g2, b2, h);

    // 7) out = 2*(h @ Wfc + bfc + x)
    gemm_tile<false, 2><<<gw, 256>>>(h, Wfc, out, bfc, x, NROWS, EE, EE, 0, 0, 0);
}

// round 12
// speedup vs baseline: 3.1352x; 3.1352x over previous
#include <cuda_runtime.h>
#include <cuda_bf16.h>
#include <cstdint>
#include <cstddef>

#define BB 8
#define SS 2048
#define EE 1024
#define NROWS (BB * SS)   // 16384

// ===========================================================================
// Scratch (device globals — allocation-guard-legal workspace)
// ===========================================================================
__device__ __align__(16) __nv_bfloat16 g_h_hi[(size_t)NROWS * EE];
__device__ __align__(16) __nv_bfloat16 g_h_lo[(size_t)NROWS * EE];
__device__ __align__(16) __nv_bfloat16 g_qk_hi[2 * (size_t)NROWS * EE]; // [q; k]
__device__ __align__(16) __nv_bfloat16 g_qk_lo[2 * (size_t)NROWS * EE];
__device__ __align__(16) float         g_v[(size_t)NROWS * EE];
__device__ __align__(16) __nv_bfloat16 g_vt_hi[(size_t)NROWS * EE];    // [B][EI][S]
__device__ __align__(16) __nv_bfloat16 g_vt_lo[(size_t)NROWS * EE];
__device__ __align__(16) float         g_s[(size_t)BB * SS * SS];
__device__ __align__(16) __nv_bfloat16 g_p_hi[(size_t)BB * SS * SS];
__device__ __align__(16) __nv_bfloat16 g_p_lo[(size_t)BB * SS * SS];
__device__ __align__(16) float         g_o[(size_t)NROWS * EE];
__device__ __align__(16) __nv_bfloat16 g_on_hi[(size_t)NROWS * EE];
__device__ __align__(16) __nv_bfloat16 g_on_lo[(size_t)NROWS * EE];
__device__ __align__(16) __nv_bfloat16 g_wt_hi[4 * (size_t)EE * EE];   // [WqT;WkT;WvT;WfcT]
__device__ __align__(16) __nv_bfloat16 g_wt_lo[4 * (size_t)EE * EE];

// ===========================================================================
// PTX helpers — sm_80-era, target-independent (NO tcgen05: harness compiles
// for compute_103, which rejects arch-'a' features)
// ===========================================================================
__device__ __forceinline__ uint32_t smem_u32(const void* p) {
    uint32_t a;
    asm("{ .reg .u64 t; cvta.to.shared.u64 t, %1; cvt.u32.u64 %0, t; }" : "=r"(a) : "l"(p));
    return a;
}
__device__ __forceinline__ void cp16(uint32_t dst, const void* src) {
    asm volatile("cp.async.cg.shared.global [%0], [%1], 16;" :: "r"(dst), "l"(src));
}
__device__ __forceinline__ void ldsm4(uint32_t& r0, uint32_t& r1, uint32_t& r2, uint32_t& r3,
                                      uint32_t addr) {
    asm volatile("ldmatrix.sync.aligned.m8n8.x4.shared.b16 {%0,%1,%2,%3}, [%4];"
                 : "=r"(r0), "=r"(r1), "=r"(r2), "=r"(r3) : "r"(addr));
}
__device__ __forceinline__ void mma16816(float* c, const uint32_t* a, const uint32_t* b) {
    asm volatile(
        "mma.sync.aligned.m16n8k16.row.col.f32.bf16.bf16.f32 "
        "{%0,%1,%2,%3}, {%4,%5,%6,%7}, {%8,%9}, {%0,%1,%2,%3};"
        : "+f"(c[0]), "+f"(c[1]), "+f"(c[2]), "+f"(c[3])
        : "r"(a[0]), "r"(a[1]), "r"(a[2]), "r"(a[3]), "r"(b[0]), "r"(b[1]));
}
__device__ __forceinline__ uint32_t pack_bf16(float a, float b) {
    __nv_bfloat162 h = __floats2bfloat162_rn(a, b);
    return *reinterpret_cast<uint32_t*>(&h);
}
__device__ __forceinline__ void split2(float a, float b, uint32_t& hi, uint32_t& lo) {
    __nv_bfloat16 ha = __float2bfloat16(a), hb = __float2bfloat16(b);
    float ra = a - __bfloat162float(ha), rb = b - __bfloat162float(hb);
    __nv_bfloat162 h2; h2.x = ha; h2.y = hb;
    hi = *reinterpret_cast<uint32_t*>(&h2);
    lo = pack_bf16(ra, rb);
}

// ===========================================================================
// bf16x3 split GEMM via mma.sync (HMMA): C[128x128 tile] = A[M,K] * B^T
// (A, B both K-major: A[M][K], B[N][K]; hi/lo bf16 split of each)
// 8 warps (4 m x 2 n), warp tile 32x64, BK=32, double-buffered cp.async.
// MODE 0: QKV fused over z: z<2 -> split bf16 out (+bias), z==2 -> f32 (+bias)
// MODE 1: plain f32 out (batched via z strides)
// MODE 3: f32 out = 2*(acc + bias + resid)
// ===========================================================================
#define KPAD 40                         // halves; 80B row stride (conflict-free ldsm)
#define OFF_AH 0
#define OFF_AL (128 * KPAD)
#define OFF_BH (2 * 128 * KPAD)
#define OFF_BL (3 * 128 * KPAD)
#define BUF_HALVES (4 * 128 * KPAD)     // 20480 halves = 40 KB
#define BUF_BYTES (BUF_HALVES * 2)
#define GEMM_SMEM (2 * BUF_BYTES)       // 80 KB

__device__ __forceinline__ void load_chunk(
    uint32_t sbuf,
    const __nv_bfloat16* __restrict__ Ah, const __nv_bfloat16* __restrict__ Al,
    const __nv_bfloat16* __restrict__ Bh, const __nv_bfloat16* __restrict__ Bl,
    long rowBase, long colBase, int K, int k0, int t)
{
    #pragma unroll
    for (int i = 0; i < 2; i++) {
        int item = t + i * 256;            // 0..511
        int r = item >> 2;                 // 0..127
        int sg = item & 3;                 // 0..3 (16B groups of the 64B k-slice)
        uint32_t so = (uint32_t)((r * KPAD + sg * 8) * 2);
        long ga = (rowBase + r) * (long)K + k0 + sg * 8;
        long gb = (colBase + r) * (long)K + k0 + sg * 8;
        cp16(sbuf + OFF_AH * 2 + so, Ah + ga);
        cp16(sbuf + OFF_AL * 2 + so, Al + ga);
        cp16(sbuf + OFF_BH * 2 + so, Bh + gb);
        cp16(sbuf + OFF_BL * 2 + so, Bl + gb);
    }
}

template <int MODE>
__global__ void __launch_bounds__(256) hgemm3(
    const __nv_bfloat16* __restrict__ Ah_, const __nv_bfloat16* __restrict__ Al_,
    const __nv_bfloat16* __restrict__ Bh_, const __nv_bfloat16* __restrict__ Bl_,
    int K, int Ncols, long sAz, long sBz, long sCz,
    float* __restrict__ Cf_, __nv_bfloat16* __restrict__ Ch_, __nv_bfloat16* __restrict__ Cl_,
    const float* __restrict__ b0, const float* __restrict__ b1, const float* __restrict__ b2,
    const float* __restrict__ resid)
{
    extern __shared__ __align__(16) char dsm[];
    const int t = threadIdx.x;
    const int wid = t >> 5, lane = t & 31;
    const int z = blockIdx.z;
    const long rowBase = (long)blockIdx.y * 128;
    const long colBase = (long)blockIdx.x * 128;

    const __nv_bfloat16* Ah = Ah_ + (long)z * sAz;
    const __nv_bfloat16* Al = Al_ + (long)z * sAz;
    const __nv_bfloat16* Bh = Bh_ + (long)z * sBz;
    const __nv_bfloat16* Bl = Bl_ + (long)z * sBz;

    const uint32_t smem = smem_u32(dsm);
    const int mw = wid & 3;       // 4 m-warps of 32 rows
    const int nw = wid >> 2;      // 2 n-warps of 64 cols

    float acc[2][8][4];
    #pragma unroll
    for (int i = 0; i < 2; i++)
        #pragma unroll
        for (int j = 0; j < 8; j++)
            #pragma unroll
            for (int k = 0; k < 4; k++) acc[i][j][k] = 0.0f;

    const int nC = K >> 5;

    load_chunk(smem, Ah, Al, Bh, Bl, rowBase, colBase, K, 0, t);
    asm volatile("cp.async.commit_group;");

    for (int c = 0; c < nC; ++c) {
        if (c + 1 < nC) {
            load_chunk(smem + ((c + 1) & 1) * BUF_BYTES, Ah, Al, Bh, Bl,
                       rowBase, colBase, K, (c + 1) << 5, t);
            asm volatile("cp.async.commit_group;");
            asm volatile("cp.async.wait_group 1;" ::: "memory");
        } else {
            asm volatile("cp.async.wait_group 0;" ::: "memory");
        }
        __syncthreads();

        const uint32_t sb = smem + (c & 1) * BUF_BYTES;
        #pragma unroll
        for (int ks = 0; ks < 2; ++ks) {
            uint32_t ah[2][4], al[2][4], bh[8][2], bl[8][2];
            // A fragments: rows = m, cols = k (plain ldmatrix)
            #pragma unroll
            for (int mt = 0; mt < 2; ++mt) {
                uint32_t row = mw * 32 + mt * 16 + (lane & 15);
                uint32_t col = ks * 16 + (lane >> 4) * 8;
                uint32_t off = (row * KPAD + col) * 2;
                ldsm4(ah[mt][0], ah[mt][1], ah[mt][2], ah[mt][3], sb + OFF_AH * 2 + off);
                ldsm4(al[mt][0], al[mt][1], al[mt][2], al[mt][3], sb + OFF_AL * 2 + off);
            }
            // B fragments: rows = n, cols = k (plain ldmatrix; [n][k] == col-major B)
            #pragma unroll
            for (int np = 0; np < 4; ++np) {
                uint32_t row = nw * 64 + np * 16 + (lane >> 4) * 8 + (lane & 7);
                uint32_t col = ks * 16 + ((lane >> 3) & 1) * 8;
                uint32_t off = (row * KPAD + col) * 2;
                uint32_t r0, r1, r2, r3;
                ldsm4(r0, r1, r2, r3, sb + OFF_BH * 2 + off);
                bh[2 * np][0] = r0; bh[2 * np][1] = r1;
                bh[2 * np + 1][0] = r2; bh[2 * np + 1][1] = r3;
                ldsm4(r0, r1, r2, r3, sb + OFF_BL * 2 + off);
                bl[2 * np][0] = r0; bl[2 * np][1] = r1;
                bl[2 * np + 1][0] = r2; bl[2 * np + 1][1] = r3;
            }
            // 3-term split product; combo-major order spaces same-acc RAW by 16 mmas
            #pragma unroll
            for (int mt = 0; mt < 2; ++mt)
                #pragma unroll
                for (int nt = 0; nt < 8; ++nt) mma16816(acc[mt][nt], ah[mt], bh[nt]);
            #pragma unroll
            for (int mt = 0; mt < 2; ++mt)
                #pragma unroll
                for (int nt = 0; nt < 8; ++nt) mma16816(acc[mt][nt], ah[mt], bl[nt]);
            #pragma unroll
            for (int mt = 0; mt < 2; ++mt)
                #pragma unroll
                for (int nt = 0; nt < 8; ++nt) mma16816(acc[mt][nt], al[mt], bh[nt]);
        }
        __syncthreads();
    }

    // ---- epilogue: direct register->gmem stores (quad-contiguous 32B/16B) ----
    const int g = lane >> 2, tg = lane & 3;
    float be[8][2];
    if (MODE == 0 || MODE == 3) {
        const float* bb = (MODE == 3) ? b0 : ((z == 0) ? b0 : ((z == 1) ? b1 : b2));
        #pragma unroll
        for (int nt = 0; nt < 8; ++nt) {
            long col = colBase + nw * 64 + nt * 8 + tg * 2;
            be[nt][0] = bb[col]; be[nt][1] = bb[col + 1];
        }
    }

    #pragma unroll
    for (int mt = 0; mt < 2; ++mt) {
        long r0 = rowBase + mw * 32 + mt * 16 + g;
        long r1 = r0 + 8;
        #pragma unroll
        for (int nt = 0; nt < 8; ++nt) {
            long col = colBase + nw * 64 + nt * 8 + tg * 2;
            float v00 = acc[mt][nt][0], v01 = acc[mt][nt][1];
            float v10 = acc[mt][nt][2], v11 = acc[mt][nt][3];
            if (MODE == 0) {
                v00 += be[nt][0]; v01 += be[nt][1];
                v10 += be[nt][0]; v11 += be[nt][1];
                if (z < 2) {
                    long o0 = (long)z * ((long)NROWS * EE) + r0 * (long)Ncols + col;
                    long o1 = (long)z * ((long)NROWS * EE) + r1 * (long)Ncols + col;
                    uint32_t h0, l0, h1, l1;
                    split2(v00, v01, h0, l0);
                    split2(v10, v11, h1, l1);
                    *reinterpret_cast<uint32_t*>(Ch_ + o0) = h0;
                    *reinterpret_cast<uint32_t*>(Cl_ + o0) = l0;
                    *reinterpret_cast<uint32_t*>(Ch_ + o1) = h1;
                    *reinterpret_cast<uint32_t*>(Cl_ + o1) = l1;
                } else {
                    *reinterpret_cast<float2*>(Cf_ + r0 * (long)Ncols + col) = make_float2(v00, v01);
                    *reinterpret_cast<float2*>(Cf_ + r1 * (long)Ncols + col) = make_float2(v10, v11);
                }
            } else if (MODE == 1) {
                float* Cz = Cf_ + (long)z * sCz;
                *reinterpret_cast<float2*>(Cz + r0 * (long)Ncols + col) = make_float2(v00, v01);
                *reinterpret_cast<float2*>(Cz + r1 * (long)Ncols + col) = make_float2(v10, v11);
            } else { // MODE 3
                long o0 = r0 * (long)Ncols + col;
                long o1 = r1 * (long)Ncols + col;
                float2 x0 = *reinterpret_cast<const float2*>(resid + o0);
                float2 x1 = *reinterpret_cast<const float2*>(resid + o1);
                *reinterpret_cast<float2*>(Cf_ + o0) =
                    make_float2(2.0f * (v00 + be[nt][0] + x0.x), 2.0f * (v01 + be[nt][1] + x0.y));
                *reinterpret_cast<float2*>(Cf_ + o1) =
                    make_float2(2.0f * (v10 + be[nt][0] + x1.x), 2.0f * (v11 + be[nt][1] + x1.y));
            }
        }
    }
}

// ===========================================================================
// Block reductions (256 threads)
// ===========================================================================
__device__ __forceinline__ float blockReduceSum(float v, float* red) {
    #pragma unroll
    for (int o = 16; o > 0; o >>= 1) v += __shfl_xor_sync(0xffffffffu, v, o);
    int t = threadIdx.x;
    if ((t & 31) == 0) red[t >> 5] = v;
    __syncthreads();
    if (t < 32) {
        float r = (t < 8) ? red[t] : 0.0f;
        #pragma unroll
        for (int o = 4; o > 0; o >>= 1) r += __shfl_xor_sync(0xffffffffu, r, o);
        if (t == 0) red[0] = r;
    }
    __syncthreads();
    float out = red[0];
    __syncthreads();
    return out;
}
__device__ __forceinline__ float blockReduceMax(float v, float* red) {
    #pragma unroll
    for (int o = 16; o > 0; o >>= 1) v = fmaxf(v, __shfl_xor_sync(0xffffffffu, v, o));
    int t = threadIdx.x;
    if ((t & 31) == 0) red[t >> 5] = v;
    __syncthreads();
    if (t < 32) {
        float r = (t < 8) ? red[t] : -3.0e38f;
        #pragma unroll
        for (int o = 4; o > 0; o >>= 1) r = fmaxf(r, __shfl_xor_sync(0xffffffffu, r, o));
        if (t == 0) red[0] = r;
    }
    __syncthreads();
    float out = red[0];
    __syncthreads();
    return out;
}

// ===========================================================================
// LayerNorm(1024) -> bf16 hi/lo split
// ===========================================================================
__global__ __launch_bounds__(256) void ln_split(const float* __restrict__ in,
                                                const float* __restrict__ gam,
                                                const float* __restrict__ bet,
                                                __nv_bfloat16* __restrict__ oh,
                                                __nv_bfloat16* __restrict__ ol) {
    __shared__ float red[8];
    const long row = blockIdx.x;
    const float* x = in + row * (long)EE;
    const int t = threadIdx.x;
    float4 xv = *reinterpret_cast<const float4*>(&x[t * 4]);

    float s = blockReduceSum(xv.x + xv.y + xv.z + xv.w, red);
    float mu = s * (1.0f / 1024.0f);
    float d0 = xv.x - mu, d1 = xv.y - mu, d2 = xv.z - mu, d3 = xv.w - mu;
    float ss = blockReduceSum(d0 * d0 + d1 * d1 + d2 * d2 + d3 * d3, red);
    float r = rsqrtf(ss * (1.0f / 1024.0f) + 1e-5f);

    float4 g4 = *reinterpret_cast<const float4*>(&gam[t * 4]);
    float4 b4 = *reinterpret_cast<const float4*>(&bet[t * 4]);
    float ov[4];
    ov[0] = d0 * r * g4.x + b4.x; ov[1] = d1 * r * g4.y + b4.y;
    ov[2] = d2 * r * g4.z + b4.z; ov[3] = d3 * r * g4.w + b4.w;

    uint32_t hw[2], lw[2];
    split2(ov[0], ov[1], hw[0], lw[0]);
    split2(ov[2], ov[3], hw[1], lw[1]);
    long base = row * (long)EE + t * 4;
    *reinterpret_cast<uint2*>(&oh[base]) = make_uint2(hw[0], hw[1]);
    *reinterpret_cast<uint2*>(&ol[base]) = make_uint2(lw[0], lw[1]);
}

// ===========================================================================
// Softmax(2048) -> bf16 hi/lo split
// ===========================================================================
__global__ __launch_bounds__(256) void softmax_split(const float* __restrict__ sc,
                                                     __nv_bfloat16* __restrict__ ph,
                                                     __nv_bfloat16* __restrict__ pl) {
    __shared__ float red[8];
    const long row = blockIdx.x;
    const float* p = sc + row * (long)SS;
    const int t = threadIdx.x;
    float4 a = *reinterpret_cast<const float4*>(&p[t * 8]);
    float4 b = *reinterpret_cast<const float4*>(&p[t * 8 + 4]);

    float m = fmaxf(fmaxf(fmaxf(a.x, a.y), fmaxf(a.z, a.w)),
                    fmaxf(fmaxf(b.x, b.y), fmaxf(b.z, b.w)));
    m = blockReduceMax(m, red);

    float e[8];
    e[0] = __expf(a.x - m); e[1] = __expf(a.y - m); e[2] = __expf(a.z - m); e[3] = __expf(a.w - m);
    e[4] = __expf(b.x - m); e[5] = __expf(b.y - m); e[6] = __expf(b.z - m); e[7] = __expf(b.w - m);

    float s = (e[0] + e[1] + e[2] + e[3]) + (e[4] + e[5] + e[6] + e[7]);
    s = blockReduceSum(s, red);
    float inv = 1.0f / s;

    uint32_t hw[4], lw[4];
    #pragma unroll
    for (int i = 0; i < 4; i++)
        split2(e[2 * i] * inv, e[2 * i + 1] * inv, hw[i], lw[i]);
    long base = row * (long)SS + t * 8;
    *reinterpret_cast<uint4*>(&ph[base]) = make_uint4(hw[0], hw[1], hw[2], hw[3]);
    *reinterpret_cast<uint4*>(&pl[base]) = make_uint4(lw[0], lw[1], lw[2], lw[3]);
}

// ===========================================================================
// Transpose + split: in[R][C] (f32) -> out[C][R] (bf16 hi/lo), batched via z
// ===========================================================================
__global__ void transpose_split(const float* __restrict__ in,
                                __nv_bfloat16* __restrict__ oh,
                                __nv_bfloat16* __restrict__ ol,
                                int R, int C, long siz, long soz) {
    __shared__ float tl[32][33];
    const float* ip = in + (long)blockIdx.z * siz;
    const int x = blockIdx.x * 32 + threadIdx.x;
    const int y0 = blockIdx.y * 32;
    #pragma unroll
    for (int j = 0; j < 32; j += 8)
        tl[threadIdx.y + j][threadIdx.x] = ip[(long)(y0 + threadIdx.y + j) * C + x];
    __syncthreads();
    #pragma unroll
    for (int j = 0; j < 32; j += 8) {
        float v = tl[threadIdx.x][threadIdx.y + j];
        __nv_bfloat16 hi = __float2bfloat16(v);
        __nv_bfloat16 lo = __float2bfloat16(v - __bfloat162float(hi));
        long o = (long)blockIdx.z * soz +
                 (long)(blockIdx.x * 32 + threadIdx.y + j) * R + y0 + threadIdx.x;
        oh[o] = hi; ol[o] = lo;
    }
}

// ===========================================================================
// Launch sequence
// ===========================================================================
extern "C" void kernel_launch(void* const* d_in, const int* in_sizes, int n_in,
                              void* d_out, int out_size) {
    const float* x   = (const float*)d_in[0];
    const float* Wq  = (const float*)d_in[1];
    const float* bq  = (const float*)d_in[2];
    const float* Wk  = (const float*)d_in[3];
    const float* bk  = (const float*)d_in[4];
    const float* Wv  = (const float*)d_in[5];
    const float* bv  = (const float*)d_in[6];
    const float* Wfc = (const float*)d_in[7];
    const float* bfc = (const float*)d_in[8];
    const float* g1  = (const float*)d_in[9];
    const float* b1  = (const float*)d_in[10];
    const float* g2  = (const float*)d_in[11];
    const float* b2  = (const float*)d_in[12];
    float* out = (float*)d_out;

    __nv_bfloat16 *hHi, *hLo, *qkHi, *qkLo, *vtHi, *vtLo, *pHi, *pLo, *onHi, *onLo, *wtHi, *wtLo;
    float *vF, *sF, *oF;
    cudaGetSymbolAddress((void**)&hHi, g_h_hi);   cudaGetSymbolAddress((void**)&hLo, g_h_lo);
    cudaGetSymbolAddress((void**)&qkHi, g_qk_hi); cudaGetSymbolAddress((void**)&qkLo, g_qk_lo);
    cudaGetSymbolAddress((void**)&vF, g_v);
    cudaGetSymbolAddress((void**)&vtHi, g_vt_hi); cudaGetSymbolAddress((void**)&vtLo, g_vt_lo);
    cudaGetSymbolAddress((void**)&sF, g_s);
    cudaGetSymbolAddress((void**)&pHi, g_p_hi);   cudaGetSymbolAddress((void**)&pLo, g_p_lo);
    cudaGetSymbolAddress((void**)&oF, g_o);
    cudaGetSymbolAddress((void**)&onHi, g_on_hi); cudaGetSymbolAddress((void**)&onLo, g_on_lo);
    cudaGetSymbolAddress((void**)&wtHi, g_wt_hi); cudaGetSymbolAddress((void**)&wtLo, g_wt_lo);

    cudaFuncSetAttribute(hgemm3<0>, cudaFuncAttributeMaxDynamicSharedMemorySize, GEMM_SMEM);
    cudaFuncSetAttribute(hgemm3<1>, cudaFuncAttributeMaxDynamicSharedMemorySize, GEMM_SMEM);
    cudaFuncSetAttribute(hgemm3<3>, cudaFuncAttributeMaxDynamicSharedMemorySize, GEMM_SMEM);

    const long EE2 = (long)EE * EE;
    dim3 tb(32, 8);

    // 0) weight transposes + splits: wt[i][n][k] = W_i[k][n]
    transpose_split<<<dim3(32, 32, 1), tb>>>(Wq,  wtHi + 0 * EE2, wtLo + 0 * EE2, EE, EE, 0, 0);
    transpose_split<<<dim3(32, 32, 1), tb>>>(Wk,  wtHi + 1 * EE2, wtLo + 1 * EE2, EE, EE, 0, 0);
    transpose_split<<<dim3(32, 32, 1), tb>>>(Wv,  wtHi + 2 * EE2, wtLo + 2 * EE2, EE, EE, 0, 0);
    transpose_split<<<dim3(32, 32, 1), tb>>>(Wfc, wtHi + 3 * EE2, wtLo + 3 * EE2, EE, EE, 0, 0);

    // 1) h = LN(x) -> splits
    ln_split<<<NROWS, 256>>>(x, g1, b1, hHi, hLo);

    // 2) fused QKV: z in {0:q split, 1:k split, 2:v f32}
    hgemm3<0><<<dim3(EE / 128, NROWS / 128, 3), 256, GEMM_SMEM>>>(
        hHi, hLo, wtHi, wtLo, EE, EE, 0, EE2, 0,
        vF, qkHi, qkLo, bq, bk, bv, nullptr);

    // 3) v transpose+split: [B][S][EI] -> [B][EI][S]
    transpose_split<<<dim3(EE / 32, SS / 32, BB), tb>>>(
        vF, vtHi, vtLo, SS, EE, (long)SS * EE, (long)EE * SS);

    // 4) scores = q @ k^T per batch (f32 out)
    hgemm3<1><<<dim3(SS / 128, SS / 128, BB), 256, GEMM_SMEM>>>(
        qkHi, qkLo, qkHi + (long)NROWS * EE, qkLo + (long)NROWS * EE,
        EE, SS, (long)SS * EE, (long)SS * EE, (long)SS * SS,
        sF, nullptr, nullptr, nullptr, nullptr, nullptr, nullptr);

    // 5) softmax + split
    softmax_split<<<BB * SS, 256>>>(sF, pHi, pLo);

    // 6) o = attn @ v per batch (B = vt[EI][S])
    hgemm3<1><<<dim3(EE / 128, SS / 128, BB), 256, GEMM_SMEM>>>(
        pHi, pLo, vtHi, vtLo,
        SS, EE, (long)SS * SS, (long)EE * SS, (long)SS * EE,
        oF, nullptr, nullptr, nullptr, nullptr, nullptr, nullptr);

    // 7) LN2 -> splits
    ln_split<<<NROWS, 256>>>(oF, g2, b2, onHi, onLo);

    // 8) out = 2*(oln @ Wfc + bfc + x)
    hgemm3<3><<<dim3(EE / 128, NROWS / 128, 1), 256, GEMM_SMEM>>>(
        onHi, onLo, wtHi + 3 * EE2, wtLo + 3 * EE2,
        EE, EE, 0, 0, 0,
        out, nullptr, nullptr, bfc, nullptr, nullptr, x);
}